// round 7
// baseline (speedup 1.0000x reference)
#include <cuda_runtime.h>

// x: [8,32,512] fp32, w_q/w_k/w_v: [1,128] fp32, out: [8,32,128] fp32
#define BV      256
#define FDIM    512
#define DMODEL  128
#define CHUNKS  4        // blocks per row
#define FC      128      // f per block
#define TPB     256      // 128 f x 2 g-halves

__device__ float    g_partial[BV * CHUNKS];
__device__ unsigned g_cnt[BV];          // zero-init; self-resetting per launch

typedef unsigned long long u64;

// ---- packed f32x2 plumbing (Blackwell sm_103a) ----
__device__ __forceinline__ u64 pack2(float a, float b) {
    u64 r; asm("mov.b64 %0, {%1, %2};" : "=l"(r) : "f"(a), "f"(b)); return r;
}
__device__ __forceinline__ float2 unpack2(u64 v) {
    float2 p; asm("mov.b64 {%0, %1}, %2;" : "=f"(p.x), "=f"(p.y) : "l"(v)); return p;
}
__device__ __forceinline__ u64 pack2u(unsigned a, unsigned b) {
    u64 r; asm("mov.b64 %0, {%1, %2};" : "=l"(r) : "r"(a), "r"(b)); return r;
}
__device__ __forceinline__ void unpack2u(u64 v, unsigned& a, unsigned& b) {
    asm("mov.b64 {%0, %1}, %2;" : "=r"(a), "=r"(b) : "l"(v));
}
__device__ __forceinline__ u64 mul2(u64 a, u64 b) {
    u64 r; asm("mul.rn.f32x2 %0, %1, %2;" : "=l"(r) : "l"(a), "l"(b)); return r;
}
__device__ __forceinline__ u64 add2(u64 a, u64 b) {
    u64 r; asm("add.rn.f32x2 %0, %1, %2;" : "=l"(r) : "l"(a), "l"(b)); return r;
}
__device__ __forceinline__ u64 fma2(u64 a, u64 b, u64 c) {
    u64 r; asm("fma.rn.f32x2 %0, %1, %2, %3;" : "=l"(r) : "l"(a), "l"(b), "l"(c)); return r;
}
__device__ __forceinline__ float ex2f(float a) {
    float r; asm("ex2.approx.ftz.f32 %0, %1;" : "=f"(r) : "f"(a)); return r;
}
__device__ __forceinline__ float ldcg(const float* p) {
    float v; asm volatile("ld.global.cg.f32 %0, [%1];" : "=f"(v) : "l"(p)); return v;
}

__global__ __launch_bounds__(TPB)
void attn_fused_kernel(const float* __restrict__ x,
                       const float* __restrict__ wq,
                       const float* __restrict__ wk,
                       const float* __restrict__ wv,
                       float* __restrict__ out)
{
    __shared__ __align__(16) float sx[FDIM];
    __shared__ float sDen[TPB];
    __shared__ float sNum[TPB];
    __shared__ float sRed[8];
    __shared__ float sK;
    __shared__ int   sLast;

    const int tid  = threadIdx.x;
    const int lane = tid & 31;
    const int warp = tid >> 5;
    const int bv   = blockIdx.x >> 2;
    const int sub  = blockIdx.x & 3;      // f-chunk of 128
    const int fi   = tid & 127;           // f within chunk
    const int gh   = tid >> 7;            // g half (0/1)
    const float* __restrict__ xr = x + bv * FDIM;

    // Stage row into smem (fp32). No max/min needed: fp32 exp2 never overflows here.
    #pragma unroll
    for (int i = 0; i < FDIM / TPB; i++)
        sx[tid + TPB * i] = xr[tid + TPB * i];

    float p = (tid < DMODEL) ? wq[tid] * wk[tid] : 0.0f;
    #pragma unroll
    for (int s = 16; s > 0; s >>= 1)
        p += __shfl_xor_sync(~0u, p, s);
    if (lane == 0) sRed[warp] = p;
    __syncthreads();
    if (tid == 0) {
        float P = (sRed[0] + sRed[1]) + (sRed[2] + sRed[3]);
        // log2(e)/sqrt(128)
        sK = P * (1.4426950408889634f * 0.08838834764831845f);
    }
    __syncthreads();

    // Per-thread logit scale t2 = c2 * x_f; logit(g) = t2 * x_g  (exp2 domain).
    const float t2   = sK * sx[sub * FC + fi];
    const u64   t2x2 = pack2(t2, t2);

    // f32x2 constants for the FFMA-exp path.
    const float MAGIC = 12582912.0f;                 // 1.5 * 2^23
    const u64 MAG2  = pack2(MAGIC, MAGIC);
    const u64 NMAG2 = pack2(-MAGIC, -MAGIC);
    const u64 NEG12 = pack2(-1.0f, -1.0f);
    // Chebyshev-economized deg-3 for 2^r on [-0.5, 0.5] (rel err ~1.3e-4)
    const u64 C32 = pack2(0.0555041f, 0.0555041f);
    const u64 C22 = pack2(0.24263040f, 0.24263040f);
    const u64 C12 = pack2(0.69314718f, 0.69314718f);
    const u64 C02 = pack2(0.99992496f, 0.99992496f);

    u64 denm = 0ull, numm = 0ull;   // MUFU-path accumulators (f32x2 pairs, start 0.0)
    u64 denf = 0ull, numf = 0ull;   // FFMA-path accumulators

    // This thread covers 256 g: 8 iterations x 32 g = (20 g MUFU + 12 g FFMA2).
    const float4* __restrict__ xb = ((const float4*)sx) + gh * 64;
    #pragma unroll
    for (int it = 0; it < 8; it++) {
        const float4* __restrict__ p4 = xb + it * 8;

        // ---- MUFU channel: 5 float4 = 20 exps ----
        #pragma unroll
        for (int j = 0; j < 5; j++) {
            float4 v = p4[j];                       // smem broadcast
            u64 xa = pack2(v.x, v.y);
            u64 xc = pack2(v.z, v.w);
            float2 la = unpack2(mul2(t2x2, xa));
            float2 lb = unpack2(mul2(t2x2, xc));
            u64 ea = pack2(ex2f(la.x), ex2f(la.y));
            u64 eb = pack2(ex2f(lb.x), ex2f(lb.y));
            denm = add2(denm, ea);
            denm = add2(denm, eb);
            numm = fma2(ea, xa, numm);
            numm = fma2(eb, xc, numm);
        }

        // ---- FFMA2 channel: 3 float4 = 12 exps (6 packed pairs) ----
        #pragma unroll
        for (int j = 5; j < 8; j++) {
            float4 v = p4[j];
            u64 xp[2] = { pack2(v.x, v.y), pack2(v.z, v.w) };
            #pragma unroll
            for (int h = 0; h < 2; h++) {
                u64 l  = mul2(t2x2, xp[h]);          // logits
                u64 t  = add2(l, MAG2);              // n = round(l) in low mantissa
                u64 s  = add2(t, NMAG2);             // s = n (as float)
                u64 r  = fma2(s, NEG12, l);          // r = l - n, in [-0.5, 0.5]
                u64 pp = fma2(C32, r, C22);
                pp = fma2(pp, r, C12);
                pp = fma2(pp, r, C02);               // 2^r approx
                unsigned tl, th, pl, ph;
                unpack2u(t, tl, th);
                unpack2u(pp, pl, ph);
                // scale by 2^n: bits += n<<23 (t_bits<<23 == n<<23 mod 2^32)
                u64 e = pack2u(pl + (tl << 23), ph + (th << 23));
                denf = add2(denf, e);
                numf = fma2(e, xp[h], numf);
            }
        }
    }

    float2 dm = unpack2(denm), df = unpack2(denf);
    float2 nm = unpack2(numm), nf = unpack2(numf);
    float den = (dm.x + dm.y) + (df.x + df.y);
    float num = (nm.x + nm.y) + (nf.x + nf.y);

    // Combine the two g-halves of each f, ratio, reduce over 128 f.
    sDen[tid] = den;
    sNum[tid] = num;
    __syncthreads();
    if (tid < FC) {
        float dTot = sDen[tid] + sDen[tid + FC];
        float nTot = sNum[tid] + sNum[tid + FC];
        float partial = nTot / dTot;                 // s_f
        #pragma unroll
        for (int s = 16; s > 0; s >>= 1)
            partial += __shfl_xor_sync(~0u, partial, s);
        if (lane == 0) sRed[warp] = partial;         // warps 0..3
    }
    __syncthreads();

    // Fused finalize via ticket over the 4 sub-blocks of this row.
    if (tid == 0) {
        g_partial[blockIdx.x] = (sRed[0] + sRed[1]) + (sRed[2] + sRed[3]);
        __threadfence();
        unsigned old = atomicAdd(&g_cnt[bv], 1u);
        sLast = (old == CHUNKS - 1);
        if (sLast) __threadfence();
    }
    __syncthreads();
    if (sLast && tid < DMODEL) {
        float m = (ldcg(&g_partial[bv * 4 + 0]) + ldcg(&g_partial[bv * 4 + 1]) +
                   ldcg(&g_partial[bv * 4 + 2]) + ldcg(&g_partial[bv * 4 + 3]))
                  * (1.0f / 512.0f);
        out[bv * DMODEL + tid] = m * wv[tid];
        if (tid == 0) g_cnt[bv] = 0;
    }
}

extern "C" void kernel_launch(void* const* d_in, const int* in_sizes, int n_in,
                              void* d_out, int out_size)
{
    const float* x  = (const float*)d_in[0];
    const float* wq = (const float*)d_in[1];
    const float* wk = (const float*)d_in[2];
    const float* wv = (const float*)d_in[3];
    float* out = (float*)d_out;

    attn_fused_kernel<<<BV * CHUNKS, TPB>>>(x, wq, wk, wv, out);
}

// round 8
// speedup vs baseline: 1.1199x; 1.1199x over previous
#include <cuda_runtime.h>

// x: [8,32,512] fp32, w_q/w_k/w_v: [1,128] fp32, out: [8,32,128] fp32
#define BV      256
#define FDIM    512
#define DMODEL  128
#define CHUNKS  4        // blocks per row
#define FC      128      // f per block
#define TPB     256      // 128 f x 2 g-halves

__device__ float    g_partial[BV * CHUNKS];
__device__ unsigned g_cnt[BV];          // zero-init; self-resetting per launch

__device__ __forceinline__ float ex2f(float a) {
    float r; asm("ex2.approx.ftz.f32 %0, %1;" : "=f"(r) : "f"(a)); return r;
}
__device__ __forceinline__ float ldcg(const float* p) {
    float v; asm volatile("ld.global.cg.f32 %0, [%1];" : "=f"(v) : "l"(p)); return v;
}

__global__ __launch_bounds__(TPB)
void attn_fused_kernel(const float* __restrict__ x,
                       const float* __restrict__ wq,
                       const float* __restrict__ wk,
                       const float* __restrict__ wv,
                       float* __restrict__ out)
{
    __shared__ __align__(16) float sx[FDIM];
    __shared__ float sDen[TPB];
    __shared__ float sNum[TPB];
    __shared__ float sRed[8];
    __shared__ float sK;
    __shared__ int   sLast;

    const int tid  = threadIdx.x;
    const int lane = tid & 31;
    const int warp = tid >> 5;
    const int bv   = blockIdx.x >> 2;
    const int sub  = blockIdx.x & 3;      // f-chunk of 128
    const int fi   = tid & 127;           // f within chunk
    const int gh   = tid >> 7;            // g half (0/1)
    const float* __restrict__ xr = x + bv * FDIM;

    // Stage row into smem. fp32 exp2 covers the full logit range: no max-sub.
    #pragma unroll
    for (int i = 0; i < FDIM / TPB; i++)
        sx[tid + TPB * i] = xr[tid + TPB * i];

    float p = (tid < DMODEL) ? wq[tid] * wk[tid] : 0.0f;
    #pragma unroll
    for (int s = 16; s > 0; s >>= 1)
        p += __shfl_xor_sync(~0u, p, s);
    if (lane == 0) sRed[warp] = p;
    __syncthreads();
    if (tid == 0) {
        float P = ((sRed[0] + sRed[1]) + (sRed[2] + sRed[3]))
                + ((sRed[4] + sRed[5]) + (sRed[6] + sRed[7]));
        sK = P * (1.4426950408889634f * 0.08838834764831845f); // log2(e)/sqrt(128)
    }
    __syncthreads();

    // Per-thread logit scale; logit(g) = t2 * x_g (exp2 domain).
    const float t2 = sK * sx[sub * FC + fi];

    // Poly-channel constants (magic round-to-int + deg-3 2^r on [-0.5,0.5]).
    const float MAGIC = 12582912.0f;      // 1.5 * 2^23
    const float C3 = 0.0555041f, Cq2 = 0.24263040f;
    const float C1 = 0.69314718f, C0 = 0.99992496f;

    // Dual accumulators per channel to break dependency chains.
    float dm0 = 0.f, dm1 = 0.f, nm0 = 0.f, nm1 = 0.f;   // MUFU channel
    float dp0 = 0.f, np0 = 0.f;                         // poly channel

    // This thread covers 256 g: 8 iterations x (7 MUFU float4 + 1 poly float4).
    const float4* __restrict__ xb = ((const float4*)sx) + gh * 64;
    #pragma unroll
    for (int it = 0; it < 8; it++) {
        const float4* __restrict__ p4 = xb + it * 8;

        // ---- MUFU channel: 7 float4 = 28 exps ----
        #pragma unroll
        for (int j = 0; j < 7; j++) {
            float4 v = p4[j];                       // smem broadcast
            float e0 = ex2f(t2 * v.x);
            float e1 = ex2f(t2 * v.y);
            float e2 = ex2f(t2 * v.z);
            float e3 = ex2f(t2 * v.w);
            dm0 += e0; dm1 += e1; dm0 += e2; dm1 += e3;
            nm0 = fmaf(e0, v.x, nm0);
            nm1 = fmaf(e1, v.y, nm1);
            nm0 = fmaf(e2, v.z, nm0);
            nm1 = fmaf(e3, v.w, nm1);
        }

        // ---- FFMA-poly channel: 1 float4 = 4 exps (all scalar fp32) ----
        {
            float4 v = p4[7];
            float vv[4] = { v.x, v.y, v.z, v.w };
            #pragma unroll
            for (int h = 0; h < 4; h++) {
                float xg = vv[h];
                float t  = fmaf(t2, xg, MAGIC);      // n = round(l) captured in t
                float s  = t - MAGIC;                // n as float (exact)
                float r  = fmaf(t2, xg, -s);         // r = l - n, in [-0.5, 0.5]
                float pp = fmaf(C3, r, Cq2);
                pp = fmaf(pp, r, C1);
                pp = fmaf(pp, r, C0);                // ~2^r
                unsigned tb = __float_as_uint(t);
                float e = __uint_as_float(__float_as_uint(pp) + (tb << 23)); // *2^n
                dp0 += e;
                np0 = fmaf(e, xg, np0);
            }
        }
    }

    float den = (dm0 + dm1) + dp0;
    float num = (nm0 + nm1) + np0;

    // Combine the two g-halves of each f, ratio, reduce over 128 f.
    sDen[tid] = den;
    sNum[tid] = num;
    __syncthreads();
    if (tid < FC) {
        float dTot = sDen[tid] + sDen[tid + FC];
        float nTot = sNum[tid] + sNum[tid + FC];
        float partial = nTot / dTot;                 // s_f
        #pragma unroll
        for (int s = 16; s > 0; s >>= 1)
            partial += __shfl_xor_sync(~0u, partial, s);
        if (lane == 0) sRed[warp] = partial;         // warps 0..3
    }
    __syncthreads();

    // Fused finalize via ticket over the 4 sub-blocks of this row.
    if (tid == 0) {
        g_partial[blockIdx.x] = (sRed[0] + sRed[1]) + (sRed[2] + sRed[3]);
        __threadfence();
        unsigned old = atomicAdd(&g_cnt[bv], 1u);
        sLast = (old == CHUNKS - 1);
        if (sLast) __threadfence();
    }
    __syncthreads();
    if (sLast && tid < DMODEL) {
        float m = (ldcg(&g_partial[bv * 4 + 0]) + ldcg(&g_partial[bv * 4 + 1]) +
                   ldcg(&g_partial[bv * 4 + 2]) + ldcg(&g_partial[bv * 4 + 3]))
                  * (1.0f / 512.0f);
        out[bv * DMODEL + tid] = m * wv[tid];
        if (tid == 0) g_cnt[bv] = 0;
    }
}

extern "C" void kernel_launch(void* const* d_in, const int* in_sizes, int n_in,
                              void* d_out, int out_size)
{
    const float* x  = (const float*)d_in[0];
    const float* wq = (const float*)d_in[1];
    const float* wk = (const float*)d_in[2];
    const float* wv = (const float*)d_in[3];
    float* out = (float*)d_out;

    attn_fused_kernel<<<BV * CHUNKS, TPB>>>(x, wq, wk, wv, out);
}

// round 9
// speedup vs baseline: 1.6575x; 1.4800x over previous
#include <cuda_runtime.h>

// x: [8,32,512] fp32, w_q/w_k/w_v: [1,128] fp32, out: [8,32,128] fp32
#define BV      256
#define FDIM    512
#define DMODEL  128
#define MNODES  64
#define TPB     1024

__device__ __forceinline__ float ex2f(float a) {
    float r; asm("ex2.approx.ftz.f32 %0, %1;" : "=f"(r) : "f"(a)); return r;
}

__global__ __launch_bounds__(TPB)
void attn_cheb_kernel(const float* __restrict__ x,
                      const float* __restrict__ wq,
                      const float* __restrict__ wk,
                      const float* __restrict__ wv,
                      float* __restrict__ out)
{
    __shared__ __align__(16) float sx[FDIM];
    __shared__ float tbl[128];          // tbl[m] = cos(pi*m/128), exact via cospif
    __shared__ float sS[MNODES];        // s(t_j) at Chebyshev nodes
    __shared__ float sC[MNODES];        // Chebyshev coefficients
    __shared__ float sRp[32], sRmx[32], sRmn[32];
    __shared__ float sK, sCen, sHinv, sMx, sMn, sMean;

    const int tid  = threadIdx.x;
    const int lane = tid & 31;
    const int warp = tid >> 5;
    const int bv   = blockIdx.x;
    const float* __restrict__ xr = x + bv * FDIM;

    // ---- Phase 1: load row, row min/max, K = (wq.wk)*log2e/sqrt(128) ----
    float v    = 0.0f;
    float lmax = -3.402823466e38f, lmin = 3.402823466e38f;
    if (tid < FDIM) {
        v = xr[tid];
        sx[tid] = v;
        lmax = v; lmin = v;
    }
    float p = (tid < DMODEL) ? wq[tid] * wk[tid] : 0.0f;
    #pragma unroll
    for (int s = 16; s > 0; s >>= 1) {
        p   += __shfl_xor_sync(~0u, p, s);
        lmax = fmaxf(lmax, __shfl_xor_sync(~0u, lmax, s));
        lmin = fminf(lmin, __shfl_xor_sync(~0u, lmin, s));
    }
    if (lane == 0) { sRp[warp] = p; sRmx[warp] = lmax; sRmn[warp] = lmin; }
    if (tid < 128) tbl[tid] = cospif((float)tid * (1.0f / 128.0f));
    __syncthreads();
    if (tid == 0) {
        float P = 0.0f, Mx = sRmx[0], Mn = sRmn[0];
        #pragma unroll
        for (int w = 0; w < 32; w++) {
            P += sRp[w];
            Mx = fmaxf(Mx, sRmx[w]);
            Mn = fminf(Mn, sRmn[w]);
        }
        float K  = P * (1.4426950408889634f * 0.08838834764831845f);
        float ta = K * Mn, tb = K * Mx;
        float cen = 0.5f * (ta + tb);
        float h   = 0.5f * fabsf(tb - ta);
        if (h < 1e-30f) h = 1e-30f;
        sK = K; sCen = cen; sHinv = 1.0f / h; sMx = Mx; sMn = Mn;
    }
    __syncthreads();

    // ---- Phase 2: sample s(t) at 64 Chebyshev nodes (warp w -> nodes w, w+32)
    const float cen = sCen, hw = 1.0f / sHinv;
    #pragma unroll
    for (int rep = 0; rep < 2; rep++) {
        int j = warp + rep * 32;                    // node index 0..63
        float tj = fmaf(hw, tbl[2 * j + 1], cen);   // cen + h*cos(pi(2j+1)/128)
        float Mj = (tj >= 0.0f) ? tj * sMx : tj * sMn;
        float den = 0.0f, num = 0.0f;
        #pragma unroll
        for (int i = 0; i < 16; i++) {              // lane-strided, conflict-free
            float xg = sx[lane + 32 * i];
            float e  = ex2f(fmaf(tj, xg, -Mj));
            den += e;
            num  = fmaf(e, xg, num);
        }
        #pragma unroll
        for (int s = 16; s > 0; s >>= 1) {
            den += __shfl_xor_sync(~0u, den, s);
            num += __shfl_xor_sync(~0u, num, s);
        }
        if (lane == 0) sS[j] = num / den;
    }
    __syncthreads();

    // ---- Phase 3: DCT -> Chebyshev coefficients (threads 0..63, k = tid) ----
    if (tid < MNODES) {
        float a = 0.0f;
        #pragma unroll 8
        for (int j = 0; j < MNODES; j++) {
            int m = (tid * (2 * j + 1)) & 255;      // angle pi*m/128 mod 2pi
            float c = (m < 128) ? tbl[m] : -tbl[m - 128];
            a = fmaf(sS[j], c, a);
        }
        a *= (2.0f / MNODES);
        if (tid == 0) a *= 0.5f;                    // c0 convention
        sC[tid] = a;
    }
    __syncthreads();

    // ---- Phase 4: Clenshaw eval s(t_f) for all 512 f ----
    float sf = 0.0f;
    if (tid < FDIM) {
        float u = (sK * sx[tid] - cen) * sHinv;
        u = fminf(fmaxf(u, -1.0f), 1.0f);
        float tu = u + u;
        float b1 = 0.0f, b2 = 0.0f;
        #pragma unroll
        for (int k = MNODES - 1; k >= 1; k--) {
            float b = fmaf(tu, b1, sC[k] - b2);
            b2 = b1; b1 = b;
        }
        sf = fmaf(u, b1, sC[0] - b2);
    }

    // ---- Phase 5: mean over f, write output row ----
    #pragma unroll
    for (int s = 16; s > 0; s >>= 1)
        sf += __shfl_xor_sync(~0u, sf, s);
    if (lane == 0) sRp[warp] = sf;
    __syncthreads();
    if (tid == 0) {
        float m = 0.0f;
        #pragma unroll
        for (int w = 0; w < 16; w++) m += sRp[w];   // warps 16-31 held zeros
        sMean = m * (1.0f / 512.0f);
    }
    __syncthreads();
    if (tid < DMODEL)
        out[bv * DMODEL + tid] = sMean * wv[tid];
}

extern "C" void kernel_launch(void* const* d_in, const int* in_sizes, int n_in,
                              void* d_out, int out_size)
{
    const float* x  = (const float*)d_in[0];
    const float* wq = (const float*)d_in[1];
    const float* wk = (const float*)d_in[2];
    const float* wv = (const float*)d_in[3];
    float* out = (float*)d_out;

    attn_cheb_kernel<<<BV, TPB>>>(x, wq, wk, wv, out);
}

// round 10
// speedup vs baseline: 2.3101x; 1.3937x over previous
#include <cuda_runtime.h>

// x: [8,32,512] fp32, w_q/w_k/w_v: [1,128] fp32, out: [8,32,128] fp32
#define BV      256
#define FDIM    512
#define DMODEL  128
#define MNODES  32
#define TPB     256
#define NW      (TPB / 32)

__device__ __forceinline__ float ex2f(float a) {
    float r; asm("ex2.approx.ftz.f32 %0, %1;" : "=f"(r) : "f"(a)); return r;
}

__global__ __launch_bounds__(TPB)
void attn_cheb_kernel(const float* __restrict__ x,
                      const float* __restrict__ wq,
                      const float* __restrict__ wk,
                      const float* __restrict__ wv,
                      float* __restrict__ out)
{
    __shared__ __align__(16) float sx[FDIM];
    __shared__ float tbl[2 * MNODES];   // tbl[m] = cos(pi*m/64)
    __shared__ float sS[MNODES];        // s(t_j) at Chebyshev nodes
    __shared__ float sC[MNODES];        // Chebyshev coefficients
    __shared__ float sRp[NW], sRmx[NW], sRmn[NW], sRs[NW];
    __shared__ float sK, sCen, sHinv, sMx, sMn, sMean;

    const int tid  = threadIdx.x;
    const int lane = tid & 31;
    const int warp = tid >> 5;
    const int bv   = blockIdx.x;
    const float* __restrict__ xr = x + bv * FDIM;

    // ---- Phase 1: load row (2/thread), row min/max, K ----
    float v0 = xr[tid], v1 = xr[tid + TPB];
    sx[tid] = v0; sx[tid + TPB] = v1;
    float lmax = fmaxf(v0, v1), lmin = fminf(v0, v1);
    float p = (tid < DMODEL) ? wq[tid] * wk[tid] : 0.0f;
    #pragma unroll
    for (int s = 16; s > 0; s >>= 1) {
        p   += __shfl_xor_sync(~0u, p, s);
        lmax = fmaxf(lmax, __shfl_xor_sync(~0u, lmax, s));
        lmin = fminf(lmin, __shfl_xor_sync(~0u, lmin, s));
    }
    if (lane == 0) { sRp[warp] = p; sRmx[warp] = lmax; sRmn[warp] = lmin; }
    if (tid < 2 * MNODES) tbl[tid] = cospif((float)tid * (1.0f / (2 * MNODES)));
    __syncthreads();
    if (tid == 0) {
        float P = 0.0f, Mx = sRmx[0], Mn = sRmn[0];
        #pragma unroll
        for (int w = 0; w < NW; w++) {
            P += sRp[w];
            Mx = fmaxf(Mx, sRmx[w]);
            Mn = fminf(Mn, sRmn[w]);
        }
        float K  = P * (1.4426950408889634f * 0.08838834764831845f); // log2e/sqrt(128)
        float ta = K * Mn, tb = K * Mx;
        float cen = 0.5f * (ta + tb);
        float h   = 0.5f * fabsf(tb - ta);
        if (h < 1e-30f) h = 1e-30f;
        sK = K; sCen = cen; sHinv = 1.0f / h; sMx = Mx; sMn = Mn;
    }
    __syncthreads();

    // ---- Phase 2: sample s(t) at 32 Chebyshev nodes; warp w -> nodes w+8r ----
    const float cen = sCen, hw = 1.0f / sHinv;
    #pragma unroll
    for (int rep = 0; rep < MNODES / NW; rep++) {
        int j = warp + rep * NW;                    // node 0..31
        float tj = fmaf(hw, tbl[2 * j + 1], cen);   // cen + h*cos(pi(2j+1)/64)
        float Mj = (tj >= 0.0f) ? tj * sMx : tj * sMn;
        float den = 0.0f, num = 0.0f;
        #pragma unroll
        for (int i = 0; i < FDIM / 32; i++) {       // lane-strided, conflict-free
            float xg = sx[lane + 32 * i];
            float e  = ex2f(fmaf(tj, xg, -Mj));
            den += e;
            num  = fmaf(e, xg, num);
        }
        #pragma unroll
        for (int s = 16; s > 0; s >>= 1) {
            den += __shfl_xor_sync(~0u, den, s);
            num += __shfl_xor_sync(~0u, num, s);
        }
        if (lane == 0) sS[j] = num / den;
    }
    __syncthreads();

    // ---- Phase 3: DCT -> coefficients (one warp, k = lane) ----
    if (warp == 0) {
        float a = 0.0f;
        #pragma unroll
        for (int j = 0; j < MNODES; j++) {
            int m = (lane * (2 * j + 1)) & (4 * MNODES - 1);  // angle pi*m/64 mod 2pi
            float c = (m < 2 * MNODES) ? tbl[m] : -tbl[m - 2 * MNODES];
            a = fmaf(sS[j], c, a);
        }
        a *= (2.0f / MNODES);
        if (lane == 0) a *= 0.5f;                   // c0 convention
        sC[lane] = a;
    }
    __syncthreads();

    // ---- Phase 4: Clenshaw eval s(t_f), 2 f per thread ----
    float sf = 0.0f;
    #pragma unroll
    for (int half = 0; half < 2; half++) {
        float u = (sK * sx[tid + half * TPB] - cen) * sHinv;
        u = fminf(fmaxf(u, -1.0f), 1.0f);
        float tu = u + u;
        float b1 = 0.0f, b2 = 0.0f;
        #pragma unroll
        for (int k = MNODES - 1; k >= 1; k--) {
            float b = fmaf(tu, b1, sC[k] - b2);
            b2 = b1; b1 = b;
        }
        sf += fmaf(u, b1, sC[0] - b2);
    }

    // ---- Phase 5: mean over f, write output row ----
    #pragma unroll
    for (int s = 16; s > 0; s >>= 1)
        sf += __shfl_xor_sync(~0u, sf, s);
    if (lane == 0) sRs[warp] = sf;
    __syncthreads();
    if (tid == 0) {
        float m = 0.0f;
        #pragma unroll
        for (int w = 0; w < NW; w++) m += sRs[w];
        sMean = m * (1.0f / 512.0f);
    }
    __syncthreads();
    if (tid < DMODEL)
        out[bv * DMODEL + tid] = sMean * wv[tid];
}

extern "C" void kernel_launch(void* const* d_in, const int* in_sizes, int n_in,
                              void* d_out, int out_size)
{
    const float* x  = (const float*)d_in[0];
    const float* wq = (const float*)d_in[1];
    const float* wk = (const float*)d_in[2];
    const float* wv = (const float*)d_in[3];
    float* out = (float*)d_out;

    attn_cheb_kernel<<<BV, TPB>>>(x, wq, wk, wv, out);
}

// round 11
// speedup vs baseline: 2.4465x; 1.0590x over previous
#include <cuda_runtime.h>

// x: [8,32,512] fp32, w_q/w_k/w_v: [1,128] fp32, out: [8,32,128] fp32
#define BV      256
#define FDIM    512
#define DMODEL  128
#define MNODES  32
#define TPB     512
#define NW      (TPB / 32)

__device__ __forceinline__ float ex2f(float a) {
    float r; asm("ex2.approx.ftz.f32 %0, %1;" : "=f"(r) : "f"(a)); return r;
}

__global__ __launch_bounds__(TPB)
void attn_cheb_kernel(const float* __restrict__ x,
                      const float* __restrict__ wq,
                      const float* __restrict__ wk,
                      const float* __restrict__ wv,
                      float* __restrict__ out)
{
    __shared__ __align__(16) float sx[FDIM];
    __shared__ float tbl[2 * MNODES];   // tbl[m] = cos(pi*m/64)
    __shared__ float sS[MNODES];        // s(t_j) at Chebyshev nodes
    __shared__ float sC[MNODES];        // Chebyshev coefficients
    __shared__ float sRp[NW], sRmx[NW], sRmn[NW], sRs[NW];
    __shared__ float sK, sCen, sHinv, sMx, sMn, sMean;

    const int tid  = threadIdx.x;
    const int lane = tid & 31;
    const int warp = tid >> 5;
    const int bv   = blockIdx.x;
    const float* __restrict__ xr = x + bv * FDIM;

    // ---- Phase 1: load row (1/thread), row min/max, K ----
    float v = xr[tid];
    sx[tid] = v;
    float lmax = v, lmin = v;
    float p = (tid < DMODEL) ? wq[tid] * wk[tid] : 0.0f;
    #pragma unroll
    for (int s = 16; s > 0; s >>= 1) {
        p   += __shfl_xor_sync(~0u, p, s);
        lmax = fmaxf(lmax, __shfl_xor_sync(~0u, lmax, s));
        lmin = fminf(lmin, __shfl_xor_sync(~0u, lmin, s));
    }
    if (lane == 0) { sRp[warp] = p; sRmx[warp] = lmax; sRmn[warp] = lmin; }
    if (tid < 2 * MNODES) tbl[tid] = cospif((float)tid * (1.0f / (2 * MNODES)));
    __syncthreads();
    if (tid == 0) {
        float P = 0.0f, Mx = sRmx[0], Mn = sRmn[0];
        #pragma unroll
        for (int w = 0; w < NW; w++) {
            P += sRp[w];
            Mx = fmaxf(Mx, sRmx[w]);
            Mn = fminf(Mn, sRmn[w]);
        }
        float K  = P * (1.4426950408889634f * 0.08838834764831845f); // log2e/sqrt(128)
        float ta = K * Mn, tb = K * Mx;
        float cen = 0.5f * (ta + tb);
        float h   = 0.5f * fabsf(tb - ta);
        if (h < 1e-30f) h = 1e-30f;
        sK = K; sCen = cen; sHinv = 1.0f / h; sMx = Mx; sMn = Mn;
    }
    __syncthreads();

    // ---- Phase 2: sample s(t) at 32 Chebyshev nodes; 2 nodes per warp ----
    const float cen = sCen, hw = 1.0f / sHinv;
    {
        // Two independent node chains, interleaved for ILP.
        const int j0 = warp, j1 = warp + NW;
        const float tj0 = fmaf(hw, tbl[2 * j0 + 1], cen);
        const float tj1 = fmaf(hw, tbl[2 * j1 + 1], cen);
        const float Mj0 = (tj0 >= 0.0f) ? tj0 * sMx : tj0 * sMn;
        const float Mj1 = (tj1 >= 0.0f) ? tj1 * sMx : tj1 * sMn;
        float den0 = 0.f, num0 = 0.f, den1 = 0.f, num1 = 0.f;
        #pragma unroll
        for (int i = 0; i < FDIM / 32; i++) {       // lane-strided, conflict-free
            float xg = sx[lane + 32 * i];
            float e0 = ex2f(fmaf(tj0, xg, -Mj0));
            float e1 = ex2f(fmaf(tj1, xg, -Mj1));
            den0 += e0;
            den1 += e1;
            num0 = fmaf(e0, xg, num0);
            num1 = fmaf(e1, xg, num1);
        }
        #pragma unroll
        for (int s = 16; s > 0; s >>= 1) {
            den0 += __shfl_xor_sync(~0u, den0, s);
            num0 += __shfl_xor_sync(~0u, num0, s);
            den1 += __shfl_xor_sync(~0u, den1, s);
            num1 += __shfl_xor_sync(~0u, num1, s);
        }
        if (lane == 0) { sS[j0] = num0 / den0; sS[j1] = num1 / den1; }
    }
    __syncthreads();

    // ---- Phase 3: DCT -> coefficients (one warp, k = lane) ----
    if (warp == 0) {
        float a = 0.0f;
        #pragma unroll
        for (int j = 0; j < MNODES; j++) {
            int m = (lane * (2 * j + 1)) & (4 * MNODES - 1);  // angle pi*m/64 mod 2pi
            float c = (m < 2 * MNODES) ? tbl[m] : -tbl[m - 2 * MNODES];
            a = fmaf(sS[j], c, a);
        }
        a *= (2.0f / MNODES);
        if (lane == 0) a *= 0.5f;                   // c0 convention
        sC[lane] = a;
    }
    __syncthreads();

    // ---- Phase 4: Clenshaw eval s(t_f), 1 f per thread ----
    float sf;
    {
        float u = (sK * sx[tid] - cen) * sHinv;
        u = fminf(fmaxf(u, -1.0f), 1.0f);
        float tu = u + u;
        float b1 = 0.0f, b2 = 0.0f;
        #pragma unroll
        for (int k = MNODES - 1; k >= 1; k--) {
            float b = fmaf(tu, b1, sC[k] - b2);
            b2 = b1; b1 = b;
        }
        sf = fmaf(u, b1, sC[0] - b2);
    }

    // ---- Phase 5: mean over f, write output row ----
    #pragma unroll
    for (int s = 16; s > 0; s >>= 1)
        sf += __shfl_xor_sync(~0u, sf, s);
    if (lane == 0) sRs[warp] = sf;
    __syncthreads();
    if (tid == 0) {
        float m = 0.0f;
        #pragma unroll
        for (int w = 0; w < NW; w++) m += sRs[w];
        sMean = m * (1.0f / 512.0f);
    }
    __syncthreads();
    if (tid < DMODEL)
        out[bv * DMODEL + tid] = sMean * wv[tid];
}

extern "C" void kernel_launch(void* const* d_in, const int* in_sizes, int n_in,
                              void* d_out, int out_size)
{
    const float* x  = (const float*)d_in[0];
    const float* wq = (const float*)d_in[1];
    const float* wk = (const float*)d_in[2];
    const float* wv = (const float*)d_in[3];
    float* out = (float*)d_out;

    attn_cheb_kernel<<<BV, TPB>>>(x, wq, wk, wv, out);
}